// round 5
// baseline (speedup 1.0000x reference)
#include <cuda_runtime.h>
#include <cuda_bf16.h>
#include <cuda_fp16.h>
#include <cstdint>

// ---------------- static device scratch (no allocs allowed) ----------------
#define MAXR   32
#define EPB    2048
#define MAXBLK 1024
#define MAXE   2000000
#define MAXN   200000
#define NFB    64          // blocks: feat->fp16 conversion
#define NZB    64          // blocks: zero the output

__device__ int g_blockhist[MAXBLK * MAXR];
__device__ int g_blockbase[MAXBLK * MAXR];
__device__ int g_off[MAXR + 1];   // edge offsets per relation
__device__ int g_gs[MAXR + 1];    // group (4-tile) offsets per relation
__device__ int2 g_srcdst[MAXE];   // packed {src, dst} grouped by relation
__device__ __align__(16) __half g_fh[MAXN * 64];       // feat as fp16
// Pre-packed B fragments (mma.m16n8k16 register order), fp16 hi/lo split.
// Layout: [rel][ks(4)][ntg(8)][lane(32)] -> uint2 {b0, b1}
__device__ __align__(16) uint2 g_wfh[MAXR * 1024];
__device__ __align__(16) uint2 g_wfl[MAXR * 1024];

// ---------------- helpers ----------------
__device__ __forceinline__ uint32_t smem_u32(const void* p) {
    uint32_t a;
    asm("{ .reg .u64 t; cvta.to.shared.u64 t, %1; cvt.u32.u64 %0, t; }"
        : "=r"(a) : "l"(p));
    return a;
}

__device__ __forceinline__ uint32_t pack_h2(__half a, __half b) {
    __half2 t = __halves2half2(a, b);
    return *reinterpret_cast<uint32_t*>(&t);
}

__device__ __forceinline__ void mma16816(float* c, const uint32_t* a, const uint32_t* b) {
    asm volatile(
        "mma.sync.aligned.m16n8k16.row.col.f32.f16.f16.f32 "
        "{%0,%1,%2,%3}, {%4,%5,%6,%7}, {%8,%9}, {%0,%1,%2,%3};"
        : "+f"(c[0]), "+f"(c[1]), "+f"(c[2]), "+f"(c[3])
        : "r"(a[0]), "r"(a[1]), "r"(a[2]), "r"(a[3]), "r"(b[0]), "r"(b[1]));
}

__device__ __forceinline__ void ldsm4(uint32_t* r, uint32_t addr) {
    asm volatile("ldmatrix.sync.aligned.m8n8.x4.shared.b16 {%0,%1,%2,%3}, [%4];"
                 : "=r"(r[0]), "=r"(r[1]), "=r"(r[2]), "=r"(r[3]) : "r"(addr));
}

__device__ __forceinline__ void red4(float* p, float a, float b, float c, float d) {
    asm volatile("red.global.add.v4.f32 [%0], {%1, %2, %3, %4};"
                 :: "l"(p), "f"(a), "f"(b), "f"(c), "f"(d) : "memory");
}

__device__ __forceinline__ void cpasync16(uint32_t dst, const void* src) {
    asm volatile("cp.async.ca.shared.global [%0], [%1], 16;"
                 :: "r"(dst), "l"(src) : "memory");
}
#define CP_COMMIT() asm volatile("cp.async.commit_group;" ::: "memory")
#define CP_WAIT(N)  asm volatile("cp.async.wait_group %0;" :: "n"(N) : "memory")

// ------- fused prep: W-frags + feat->fp16 + zero(out) + per-block hist ------
__global__ void k_prep_hist(const float* __restrict__ w, const float* __restrict__ feat,
                            const int* __restrict__ et, float* __restrict__ out,
                            int E, int R, int nfeat, int nout) {
    int bid = blockIdx.x;
    if (bid < R) {
        int r = bid;
        const float* wr = w + r * 4096;
        for (int idx = threadIdx.x; idx < 1024; idx += blockDim.x) {
            int lane = idx & 31, ntg = (idx >> 5) & 7, ks = idx >> 8;
            int h = ntg >> 2, nt = ntg & 3, q = lane >> 2;
            int n = h * 32 + (q >> 1) * 8 + nt * 2 + (q & 1);
            int k0 = ks * 16 + 2 * (lane & 3);
            float w00 = wr[k0 * 64 + n],       w01 = wr[(k0 + 1) * 64 + n];
            float w10 = wr[(k0 + 8) * 64 + n], w11 = wr[(k0 + 9) * 64 + n];
            __half h00 = __float2half_rn(w00), h01 = __float2half_rn(w01);
            __half h10 = __float2half_rn(w10), h11 = __float2half_rn(w11);
            __half l00 = __float2half_rn(w00 - __half2float(h00));
            __half l01 = __float2half_rn(w01 - __half2float(h01));
            __half l10 = __float2half_rn(w10 - __half2float(h10));
            __half l11 = __float2half_rn(w11 - __half2float(h11));
            g_wfh[r * 1024 + idx] = make_uint2(pack_h2(h00, h01), pack_h2(h10, h11));
            g_wfl[r * 1024 + idx] = make_uint2(pack_h2(l00, l01), pack_h2(l10, l11));
        }
    } else if (bid < R + NFB) {
        for (int i = (bid - R) * blockDim.x + threadIdx.x; i < nfeat / 2;
             i += NFB * blockDim.x) {
            float2 v = ((const float2*)feat)[i];
            ((uint32_t*)g_fh)[i] = pack_h2(__float2half_rn(v.x), __float2half_rn(v.y));
        }
    } else if (bid < R + NFB + NZB) {
        float4 z = make_float4(0.f, 0.f, 0.f, 0.f);
        for (int i = (bid - R - NFB) * blockDim.x + threadIdx.x; i < nout / 4;
             i += NZB * blockDim.x)
            ((float4*)out)[i] = z;
    } else {
        __shared__ int h[MAXR];
        int hb = bid - R - NFB - NZB;
        if (threadIdx.x < MAXR) h[threadIdx.x] = 0;
        __syncthreads();
        int start = hb * EPB, end = min(start + EPB, E);
        for (int i = start + threadIdx.x; i < end; i += blockDim.x)
            atomicAdd(&h[et[i]], 1);
        __syncthreads();
        if (threadIdx.x < MAXR)
            g_blockhist[hb * MAXR + threadIdx.x] = h[threadIdx.x];
    }
}

// ---------------- scan + group offsets ----------------
__global__ void k_scan(int nblocks, int R) {
    __shared__ int tot[MAXR], off[MAXR + 1];
    int r = threadIdx.x;
    int s = 0;
    if (r < R)
        for (int b = 0; b < nblocks; b++) s += g_blockhist[b * MAXR + r];
    if (r < MAXR) tot[r] = s;
    __syncwarp();
    if (r == 0) {
        int acc = 0;
        for (int i = 0; i < R; i++) { off[i] = acc; acc += tot[i]; }
        off[R] = acc;
        int gs = 0;
        for (int i = 0; i < R; i++) {
            g_gs[i] = gs;
            int tiles = (tot[i] + 127) >> 7;
            gs += (tiles + 3) >> 2;           // groups of 4 tiles
        }
        g_gs[R] = gs;
        for (int i = 0; i <= R; i++) g_off[i] = off[i];
    }
    __syncwarp();
    if (r < R) {
        int base = off[r];
        for (int b = 0; b < nblocks; b++) {
            g_blockbase[b * MAXR + r] = base;
            base += g_blockhist[b * MAXR + r];
        }
    }
}

// scatter with warp-aggregated smem atomics (match_any on relation)
__global__ void k_scatter(const int* __restrict__ et, const int* __restrict__ src,
                          const int* __restrict__ dst, int E) {
    __shared__ int cur[MAXR];
    if (threadIdx.x < MAXR)
        cur[threadIdx.x] = g_blockbase[blockIdx.x * MAXR + threadIdx.x];
    __syncthreads();
    int start = blockIdx.x * EPB, end = min(start + EPB, E);
    for (int i = start + threadIdx.x; i < end; i += blockDim.x) {
        int r = et[i];
        unsigned act = __activemask();
        unsigned mask = __match_any_sync(act, r);
        int leader = __ffs(mask) - 1;
        int rank = __popc(mask & ((1u << (threadIdx.x & 31)) - 1));
        int base = 0;
        if ((int)(threadIdx.x & 31) == leader)
            base = atomicAdd(&cur[r], __popc(mask));
        base = __shfl_sync(act, base, leader);
        g_srcdst[base + rank] = make_int2(src[i], dst[i]);
    }
}

// ---------------- main ----------------
// SMEM: A fp16 128x128B double-buffered (XOR-swizzled 16B chunks);
// B frag hi 8KB + lo 8KB; dst double-buffered; ctrl.
#define SM_A0   0
#define SM_A1   16384
#define SM_BH   32768
#define SM_BL   40960
#define SM_DST0 49152
#define SM_DST1 49664
#define SM_CTRL 50176
#define SMEM_SZ 50192

__global__ __launch_bounds__(256, 4) void k_main(float* __restrict__ out, int R)
{
    extern __shared__ char smem[];
    int tid = threadIdx.x;

    if ((int)blockIdx.x >= g_gs[R]) return;

    uint32_t sbase = smem_u32(smem);
    int* ctrl = (int*)(smem + SM_CTRL);
    if (tid == 0) {
        int b = blockIdx.x, r = 0;
        while (b >= g_gs[r + 1]) r++;
        int tile0 = (b - g_gs[r]) * 4;
        int ebase = g_off[r] + tile0 * 128;
        int erem = g_off[r + 1] - ebase;
        ctrl[0] = r;
        ctrl[1] = ebase;
        ctrl[2] = erem;
        ctrl[3] = min(4, (erem + 127) >> 7);
    }
    __syncthreads();
    int rel = ctrl[0], ebase = ctrl[1], erem = ctrl[2], ntile = ctrl[3];

    // ---- prologue: B frags + tile-0 gather in one cp.async group ----
    {
        const char* gh = (const char*)(g_wfh + (size_t)rel * 1024);
        const char* gl = (const char*)(g_wfl + (size_t)rel * 1024);
        int o = tid * 16;
        cpasync16(sbase + SM_BH + o, gh + o);
        cpasync16(sbase + SM_BH + 4096 + o, gh + 4096 + o);
        cpasync16(sbase + SM_BL + o, gl + o);
        cpasync16(sbase + SM_BL + 4096 + o, gl + 4096 + o);
    }
    {
        int row = tid >> 1, half = tid & 1;
        int cnt0 = min(128, erem);
        if (row < cnt0) {
            int2 e = g_srcdst[ebase + row];
            if (half == 0) ((int*)(smem + SM_DST0))[row] = e.y;
            const char* gp = (const char*)(g_fh + (size_t)e.x * 64);
#pragma unroll
            for (int i = 0; i < 4; i++) {
                int c = half * 4 + i;
                cpasync16(sbase + SM_A0 + row * 128 + ((c ^ (row & 7)) << 4),
                          gp + c * 16);
            }
        } else {
            if (half == 0) ((int*)(smem + SM_DST0))[row] = 0;
            uint4 z = make_uint4(0, 0, 0, 0);
#pragma unroll
            for (int i = 0; i < 4; i++) {
                int c = half * 4 + i;
                *(uint4*)(smem + SM_A0 + row * 128 + ((c ^ (row & 7)) << 4)) = z;
            }
        }
    }
    CP_COMMIT();

    int w = tid >> 5, lane = tid & 31;
    int mrow = (w & 3) * 32, h = w >> 2;
    int q = lane >> 2, m = lane & 3;
    int lrow = (lane & 7) + ((lane >> 3) & 1) * 8;
    int lkh = lane >> 4;

    for (int t = 0; t < ntile; t++) {
        int cnt = min(128, erem - t * 128);
        int abuf = (t & 1) ? SM_A1 : SM_A0;
        int dbuf = (t & 1) ? SM_DST1 : SM_DST0;

        // prefetch tile t+1 into the other buffer
        if (t + 1 < ntile) {
            int nbuf = ((t + 1) & 1) ? SM_A1 : SM_A0;
            int ndst = ((t + 1) & 1) ? SM_DST1 : SM_DST0;
            int cnt1 = min(128, erem - (t + 1) * 128);
            int row = tid >> 1, half = tid & 1;
            if (row < cnt1) {
                int2 e = g_srcdst[ebase + (t + 1) * 128 + row];
                if (half == 0) ((int*)(smem + ndst))[row] = e.y;
                const char* gp = (const char*)(g_fh + (size_t)e.x * 64);
#pragma unroll
                for (int i = 0; i < 4; i++) {
                    int c = half * 4 + i;
                    cpasync16(sbase + nbuf + row * 128 + ((c ^ (row & 7)) << 4),
                              gp + c * 16);
                }
            } else {
                if (half == 0) ((int*)(smem + ndst))[row] = 0;
                uint4 z = make_uint4(0, 0, 0, 0);
#pragma unroll
                for (int i = 0; i < 4; i++) {
                    int c = half * 4 + i;
                    *(uint4*)(smem + nbuf + row * 128 + ((c ^ (row & 7)) << 4)) = z;
                }
            }
            CP_COMMIT();
            CP_WAIT(1);     // tile t (and B) complete
        } else {
            CP_WAIT(0);
        }
        __syncthreads();

        // ---- compute: warp tile 32 rows x 32 cols, 2-term fp16 ----
        float acc[2][4][4];
#pragma unroll
        for (int a = 0; a < 2; a++)
#pragma unroll
            for (int b = 0; b < 4; b++)
#pragma unroll
                for (int c = 0; c < 4; c++) acc[a][b][c] = 0.0f;

#pragma unroll
        for (int ks = 0; ks < 4; ks++) {
            int kchunk = ks * 2 + lkh;
            uint32_t af[2][4];
#pragma unroll
            for (int mt = 0; mt < 2; mt++) {
                int arow = mrow + mt * 16 + lrow;
                ldsm4(af[mt], sbase + abuf + arow * 128 + ((kchunk ^ (arow & 7)) << 4));
            }
            const uint2* Bh = (const uint2*)(smem + SM_BH) + (ks * 8 + h * 4) * 32 + lane;
            const uint2* Bl = (const uint2*)(smem + SM_BL) + (ks * 8 + h * 4) * 32 + lane;
#pragma unroll
            for (int nt = 0; nt < 4; nt++) {
                uint2 bh = Bh[nt * 32];
                uint2 bl = Bl[nt * 32];
#pragma unroll
                for (int mt = 0; mt < 2; mt++) {
                    mma16816(acc[mt][nt], af[mt], (const uint32_t*)&bh);  // F*Wh
                    mma16816(acc[mt][nt], af[mt], (const uint32_t*)&bl);  // F*Wl
                }
            }
        }

        // ---- epilogue: 8 red.v4 per thread, 8 consecutive cols per row ----
        const int* db = (const int*)(smem + dbuf);
#pragma unroll
        for (int mt = 0; mt < 2; mt++)
#pragma unroll
            for (int hf = 0; hf < 2; hf++) {
                int row = mrow + mt * 16 + hf * 8 + q;
                if (row < cnt) {
                    int j = hf * 2;
                    float* o = out + (size_t)db[row] * 64 + h * 32 + m * 8;
                    red4(o,     acc[mt][0][j], acc[mt][0][j + 1],
                                acc[mt][1][j], acc[mt][1][j + 1]);
                    red4(o + 4, acc[mt][2][j], acc[mt][2][j + 1],
                                acc[mt][3][j], acc[mt][3][j + 1]);
                }
            }
        __syncthreads();   // buffer free before next prefetch overwrites it
    }
}

// ---------------- launch ----------------
extern "C" void kernel_launch(void* const* d_in, const int* in_sizes, int n_in,
                              void* d_out, int out_size) {
    const float* feat   = (const float*)d_in[0];
    const float* weight = (const float*)d_in[1];
    const int*   src    = (const int*)d_in[2];
    const int*   dst    = (const int*)d_in[3];
    const int*   et     = (const int*)d_in[4];

    int E = in_sizes[2];
    int R = in_sizes[1] / 4096;   // 64*64 per relation
    int nfeat = in_sizes[0];
    float* out = (float*)d_out;

    int nblocks = (E + EPB - 1) / EPB;
    k_prep_hist<<<R + NFB + NZB + nblocks, 256>>>(weight, feat, et, out,
                                                  E, R, nfeat, out_size);
    k_scan<<<1, 32>>>(nblocks, R);
    k_scatter<<<nblocks, 256>>>(et, src, dst, E);

    int ngroups = (E + 511) / 512 + R;   // upper bound; extras exit via g_gs[R]
    static int smem_set = 0;
    if (!smem_set) {
        cudaFuncSetAttribute(k_main, cudaFuncAttributeMaxDynamicSharedMemorySize, SMEM_SZ);
        smem_set = 1;
    }
    k_main<<<ngroups, 256, SMEM_SZ>>>(out, R);
}

// round 6
// speedup vs baseline: 1.0462x; 1.0462x over previous
#include <cuda_runtime.h>
#include <cuda_bf16.h>
#include <cuda_fp16.h>
#include <cstdint>

// ---------------- static device scratch (no allocs allowed) ----------------
#define MAXR   32
#define EPB    4096
#define MAXBLK 1024
#define MAXE   2000000
#define MAXN   200000
#define NFB    64          // blocks: feat->fp16 conversion
#define NZB    64          // blocks: zero the output

__device__ int g_blockhist[MAXBLK * MAXR];
__device__ int g_blockbase[MAXBLK * MAXR];
__device__ int g_off[MAXR + 1];   // edge offsets per relation
__device__ int g_gs[MAXR + 1];    // group (4-tile) offsets per relation
__device__ int2 g_srcdst[MAXE];   // packed {src, dst} grouped by relation
__device__ __align__(16) __half g_fh[MAXN * 64];       // feat as fp16
// Pre-packed B fragments (mma.m16n8k16 register order), fp16 hi/lo split.
// Layout: [rel][ks(4)][ntg(8)][lane(32)] -> uint2 {b0, b1}
__device__ __align__(16) uint2 g_wfh[MAXR * 1024];
__device__ __align__(16) uint2 g_wfl[MAXR * 1024];

// ---------------- helpers ----------------
__device__ __forceinline__ uint32_t smem_u32(const void* p) {
    uint32_t a;
    asm("{ .reg .u64 t; cvta.to.shared.u64 t, %1; cvt.u32.u64 %0, t; }"
        : "=r"(a) : "l"(p));
    return a;
}

__device__ __forceinline__ uint32_t pack_h2(__half a, __half b) {
    __half2 t = __halves2half2(a, b);
    return *reinterpret_cast<uint32_t*>(&t);
}

__device__ __forceinline__ void mma16816(float* c, const uint32_t* a, const uint32_t* b) {
    asm volatile(
        "mma.sync.aligned.m16n8k16.row.col.f32.f16.f16.f32 "
        "{%0,%1,%2,%3}, {%4,%5,%6,%7}, {%8,%9}, {%0,%1,%2,%3};"
        : "+f"(c[0]), "+f"(c[1]), "+f"(c[2]), "+f"(c[3])
        : "r"(a[0]), "r"(a[1]), "r"(a[2]), "r"(a[3]), "r"(b[0]), "r"(b[1]));
}

__device__ __forceinline__ void ldsm4(uint32_t* r, uint32_t addr) {
    asm volatile("ldmatrix.sync.aligned.m8n8.x4.shared.b16 {%0,%1,%2,%3}, [%4];"
                 : "=r"(r[0]), "=r"(r[1]), "=r"(r[2]), "=r"(r[3]) : "r"(addr));
}

__device__ __forceinline__ void red4(float* p, float a, float b, float c, float d) {
    asm volatile("red.global.add.v4.f32 [%0], {%1, %2, %3, %4};"
                 :: "l"(p), "f"(a), "f"(b), "f"(c), "f"(d) : "memory");
}

// 128B-granular bulk async copy with mbarrier transaction accounting (sm_90+)
__device__ __forceinline__ void bulkcp(uint32_t dst, const void* src,
                                       uint32_t bytes, uint32_t mbar) {
    asm volatile(
        "cp.async.bulk.shared::cluster.global.mbarrier::complete_tx::bytes "
        "[%0], [%1], %2, [%3];"
        :: "r"(dst), "l"(src), "r"(bytes), "r"(mbar) : "memory");
}

__device__ __forceinline__ void mbar_init(uint32_t mbar, uint32_t cnt) {
    asm volatile("mbarrier.init.shared.b64 [%0], %1;" :: "r"(mbar), "r"(cnt) : "memory");
}

__device__ __forceinline__ void mbar_expect(uint32_t mbar, uint32_t tx) {
    asm volatile("mbarrier.arrive.expect_tx.shared.b64 _, [%0], %1;"
                 :: "r"(mbar), "r"(tx) : "memory");
}

__device__ __forceinline__ void mbar_wait(uint32_t mbar, uint32_t parity) {
    asm volatile(
        "{\n\t.reg .pred P1;\n\t"
        "WAIT_%=:\n\t"
        "mbarrier.try_wait.parity.acquire.cta.shared::cta.b64 P1, [%0], %1, 0x989680;\n\t"
        "@P1 bra.uni DONE_%=;\n\t"
        "bra.uni WAIT_%=;\n\t"
        "DONE_%=:\n\t}"
        :: "r"(mbar), "r"(parity) : "memory");
}

// ------- fused prep: W-frags + feat->fp16 + zero(out) + per-block hist ------
__global__ void k_prep_hist(const float* __restrict__ w, const float* __restrict__ feat,
                            const int* __restrict__ et, float* __restrict__ out,
                            int E, int R, int nfeat, int nout) {
    int bid = blockIdx.x;
    if (bid < R) {
        int r = bid;
        const float* wr = w + r * 4096;
        for (int idx = threadIdx.x; idx < 1024; idx += blockDim.x) {
            int lane = idx & 31, ntg = (idx >> 5) & 7, ks = idx >> 8;
            int h = ntg >> 2, nt = ntg & 3, q = lane >> 2;
            int n = h * 32 + (q >> 1) * 8 + nt * 2 + (q & 1);
            int k0 = ks * 16 + 2 * (lane & 3);
            float w00 = wr[k0 * 64 + n],       w01 = wr[(k0 + 1) * 64 + n];
            float w10 = wr[(k0 + 8) * 64 + n], w11 = wr[(k0 + 9) * 64 + n];
            __half h00 = __float2half_rn(w00), h01 = __float2half_rn(w01);
            __half h10 = __float2half_rn(w10), h11 = __float2half_rn(w11);
            __half l00 = __float2half_rn(w00 - __half2float(h00));
            __half l01 = __float2half_rn(w01 - __half2float(h01));
            __half l10 = __float2half_rn(w10 - __half2float(h10));
            __half l11 = __float2half_rn(w11 - __half2float(h11));
            g_wfh[r * 1024 + idx] = make_uint2(pack_h2(h00, h01), pack_h2(h10, h11));
            g_wfl[r * 1024 + idx] = make_uint2(pack_h2(l00, l01), pack_h2(l10, l11));
        }
    } else if (bid < R + NFB) {
        for (int i = (bid - R) * blockDim.x + threadIdx.x; i < nfeat / 2;
             i += NFB * blockDim.x) {
            float2 v = ((const float2*)feat)[i];
            ((uint32_t*)g_fh)[i] = pack_h2(__float2half_rn(v.x), __float2half_rn(v.y));
        }
    } else if (bid < R + NFB + NZB) {
        float4 z = make_float4(0.f, 0.f, 0.f, 0.f);
        for (int i = (bid - R - NFB) * blockDim.x + threadIdx.x; i < nout / 4;
             i += NZB * blockDim.x)
            ((float4*)out)[i] = z;
    } else {
        __shared__ int h[MAXR];
        int hb = bid - R - NFB - NZB;
        if (threadIdx.x < MAXR) h[threadIdx.x] = 0;
        __syncthreads();
        int start = hb * EPB, end = min(start + EPB, E);
        for (int i = start + threadIdx.x; i < end; i += blockDim.x)
            atomicAdd(&h[et[i]], 1);
        __syncthreads();
        if (threadIdx.x < MAXR)
            g_blockhist[hb * MAXR + threadIdx.x] = h[threadIdx.x];
    }
}

// ------- parallel scan: warp r owns relation r, lanes chunk the blocks ------
__global__ void k_scan(int nblocks, int R) {
    __shared__ int tot[MAXR];
    __shared__ int off[MAXR + 1];
    int w = threadIdx.x >> 5, j = threadIdx.x & 31;
    int C = (nblocks + 31) / 32;
    int b0 = min(j * C, nblocks), b1 = min(b0 + C, nblocks);
    int s = 0;
    if (w < R)
        for (int b = b0; b < b1; b++) s += g_blockhist[b * MAXR + w];
    int ssum = s;
#pragma unroll
    for (int d = 1; d < 32; d <<= 1) {
        int v = __shfl_up_sync(0xffffffffu, ssum, d);
        if (j >= d) ssum += v;
    }
    int total = __shfl_sync(0xffffffffu, ssum, 31);
    int excl = ssum - s;
    if (w < R && j == 0) tot[w] = total;
    __syncthreads();
    if (threadIdx.x == 0) {
        int acc = 0, gs = 0;
        for (int i = 0; i < R; i++) {
            off[i] = acc; g_off[i] = acc; acc += tot[i];
            g_gs[i] = gs; gs += (((tot[i] + 127) >> 7) + 3) >> 2;
        }
        off[R] = acc; g_off[R] = acc; g_gs[R] = gs;
    }
    __syncthreads();
    if (w < R) {
        int base = off[w] + excl;
        for (int b = b0; b < b1; b++) {
            g_blockbase[b * MAXR + w] = base;
            base += g_blockhist[b * MAXR + w];
        }
    }
}

// scatter with warp-aggregated smem atomics (match_any on relation)
__global__ void k_scatter(const int* __restrict__ et, const int* __restrict__ src,
                          const int* __restrict__ dst, int E) {
    __shared__ int cur[MAXR];
    if (threadIdx.x < MAXR)
        cur[threadIdx.x] = g_blockbase[blockIdx.x * MAXR + threadIdx.x];
    __syncthreads();
    int start = blockIdx.x * EPB, end = min(start + EPB, E);
    for (int i = start + threadIdx.x; i < end; i += blockDim.x) {
        int r = et[i];
        unsigned act = __activemask();
        unsigned mask = __match_any_sync(act, r);
        int leader = __ffs(mask) - 1;
        int rank = __popc(mask & ((1u << (threadIdx.x & 31)) - 1));
        int base = 0;
        if ((int)(threadIdx.x & 31) == leader)
            base = atomicAdd(&cur[r], __popc(mask));
        base = __shfl_sync(act, base, leader);
        g_srcdst[base + rank] = make_int2(src[i], dst[i]);
    }
}

// ---------------- main ----------------
// SMEM: A fp16 128 rows x 144B pitch, double-buffered (bulk-copied, unswizzled;
// pitch 144 keeps ldmatrix conflict-free); B frag hi+lo 16KB; dst x2; mbar x2.
#define APITCH  144
#define SM_A0   0              // 128*144 = 18432
#define SM_A1   18432
#define SM_BH   36864
#define SM_BL   45056
#define SM_DST0 53248
#define SM_DST1 53760
#define SM_CTRL 54272
#define SM_MBAR 54288          // two b64 mbarriers
#define SMEM_SZ 54336

__global__ __launch_bounds__(256, 4) void k_main(float* __restrict__ out, int R)
{
    extern __shared__ char smem[];
    int tid = threadIdx.x;

    if ((int)blockIdx.x >= g_gs[R]) return;

    uint32_t sbase = smem_u32(smem);
    uint32_t mb0 = sbase + SM_MBAR, mb1 = sbase + SM_MBAR + 8;
    int* ctrl = (int*)(smem + SM_CTRL);
    if (tid == 0) {
        int b = blockIdx.x, r = 0;
        while (b >= g_gs[r + 1]) r++;
        int tile0 = (b - g_gs[r]) * 4;
        int ebase = g_off[r] + tile0 * 128;
        int erem = g_off[r + 1] - ebase;
        ctrl[0] = r;
        ctrl[1] = ebase;
        ctrl[2] = erem;
        ctrl[3] = min(4, (erem + 127) >> 7);
        mbar_init(mb0, 1);
        mbar_init(mb1, 1);
    }
    __syncthreads();
    int rel = ctrl[0], ebase = ctrl[1], erem = ctrl[2], ntile = ctrl[3];

    // ---- prologue: B (2 bulk copies) + tile-0 rows (128 bulk copies) ----
    {
        int cnt0 = min(128, erem);
        if (tid == 0) {
            mbar_expect(mb0, 16384u + (uint32_t)cnt0 * 128u);
            bulkcp(sbase + SM_BH, g_wfh + (size_t)rel * 1024, 8192, mb0);
            bulkcp(sbase + SM_BL, g_wfl + (size_t)rel * 1024, 8192, mb0);
        }
        if (tid < 128) {
            int row = tid;
            if (row < cnt0) {
                int2 e = g_srcdst[ebase + row];
                ((int*)(smem + SM_DST0))[row] = e.y;
                bulkcp(sbase + SM_A0 + row * APITCH,
                       g_fh + (size_t)e.x * 64, 128, mb0);
            } else {
                ((int*)(smem + SM_DST0))[row] = 0;
                uint4 z = make_uint4(0, 0, 0, 0);
#pragma unroll
                for (int i = 0; i < 8; i++)
                    *(uint4*)(smem + SM_A0 + row * APITCH + i * 16) = z;
            }
        }
    }

    int w = tid >> 5, lane = tid & 31;
    int mrow = (w & 3) * 32, h = w >> 2;
    int q = lane >> 2, m = lane & 3;
    int lrow = (lane & 7) + ((lane >> 3) & 1) * 8;
    int lkh = lane >> 4;

    for (int t = 0; t < ntile; t++) {
        int cnt = min(128, erem - t * 128);
        int abuf = (t & 1) ? SM_A1 : SM_A0;
        int dbuf = (t & 1) ? SM_DST1 : SM_DST0;

        // prefetch tile t+1 into the other buffer (other mbarrier)
        if (t + 1 < ntile) {
            int nbuf = ((t + 1) & 1) ? SM_A1 : SM_A0;
            int ndst = ((t + 1) & 1) ? SM_DST1 : SM_DST0;
            uint32_t nmb = ((t + 1) & 1) ? mb1 : mb0;
            int cnt1 = min(128, erem - (t + 1) * 128);
            if (tid == 0) mbar_expect(nmb, (uint32_t)cnt1 * 128u);
            if (tid < 128) {
                int row = tid;
                if (row < cnt1) {
                    int2 e = g_srcdst[ebase + (t + 1) * 128 + row];
                    ((int*)(smem + ndst))[row] = e.y;
                    bulkcp(sbase + nbuf + row * APITCH,
                           g_fh + (size_t)e.x * 64, 128, nmb);
                } else {
                    ((int*)(smem + ndst))[row] = 0;
                    uint4 z = make_uint4(0, 0, 0, 0);
#pragma unroll
                    for (int i = 0; i < 8; i++)
                        *(uint4*)(smem + nbuf + row * APITCH + i * 16) = z;
                }
            }
        }

        // wait tile t's data
        mbar_wait((t & 1) ? mb1 : mb0, (t >> 1) & 1);
        __syncthreads();

        // ---- compute: warp tile 32 rows x 32 cols, 2-term fp16 ----
        float acc[2][4][4];
#pragma unroll
        for (int a = 0; a < 2; a++)
#pragma unroll
            for (int b = 0; b < 4; b++)
#pragma unroll
                for (int c = 0; c < 4; c++) acc[a][b][c] = 0.0f;

#pragma unroll
        for (int ks = 0; ks < 4; ks++) {
            int kchunk = ks * 2 + lkh;
            uint32_t af[2][4];
#pragma unroll
            for (int mt = 0; mt < 2; mt++) {
                int arow = mrow + mt * 16 + lrow;
                ldsm4(af[mt], sbase + abuf + arow * APITCH + kchunk * 16);
            }
            const uint2* Bh = (const uint2*)(smem + SM_BH) + (ks * 8 + h * 4) * 32 + lane;
            const uint2* Bl = (const uint2*)(smem + SM_BL) + (ks * 8 + h * 4) * 32 + lane;
#pragma unroll
            for (int nt = 0; nt < 4; nt++) {
                uint2 bh = Bh[nt * 32];
                uint2 bl = Bl[nt * 32];
#pragma unroll
                for (int mt = 0; mt < 2; mt++) {
                    mma16816(acc[mt][nt], af[mt], (const uint32_t*)&bh);  // F*Wh
                    mma16816(acc[mt][nt], af[mt], (const uint32_t*)&bl);  // F*Wl
                }
            }
        }

        // ---- epilogue: 8 red.v4 per thread, 8 consecutive cols per row ----
        const int* db = (const int*)(smem + dbuf);
#pragma unroll
        for (int mt = 0; mt < 2; mt++)
#pragma unroll
            for (int hf = 0; hf < 2; hf++) {
                int row = mrow + mt * 16 + hf * 8 + q;
                if (row < cnt) {
                    int j = hf * 2;
                    float* o = out + (size_t)db[row] * 64 + h * 32 + m * 8;
                    red4(o,     acc[mt][0][j], acc[mt][0][j + 1],
                                acc[mt][1][j], acc[mt][1][j + 1]);
                    red4(o + 4, acc[mt][2][j], acc[mt][2][j + 1],
                                acc[mt][3][j], acc[mt][3][j + 1]);
                }
            }
        __syncthreads();   // buffer free before next prefetch overwrites it
    }
}

// ---------------- launch ----------------
extern "C" void kernel_launch(void* const* d_in, const int* in_sizes, int n_in,
                              void* d_out, int out_size) {
    const float* feat   = (const float*)d_in[0];
    const float* weight = (const float*)d_in[1];
    const int*   src    = (const int*)d_in[2];
    const int*   dst    = (const int*)d_in[3];
    const int*   et     = (const int*)d_in[4];

    int E = in_sizes[2];
    int R = in_sizes[1] / 4096;   // 64*64 per relation
    int nfeat = in_sizes[0];
    float* out = (float*)d_out;

    int nblocks = (E + EPB - 1) / EPB;
    k_prep_hist<<<R + NFB + NZB + nblocks, 256>>>(weight, feat, et, out,
                                                  E, R, nfeat, out_size);
    k_scan<<<1, 1024>>>(nblocks, R);
    k_scatter<<<nblocks, 256>>>(et, src, dst, E);

    int ngroups = (E + 511) / 512 + R;   // upper bound; extras exit via g_gs[R]
    static int smem_set = 0;
    if (!smem_set) {
        cudaFuncSetAttribute(k_main, cudaFuncAttributeMaxDynamicSharedMemorySize, SMEM_SZ);
        smem_set = 1;
    }
    k_main<<<ngroups, 256, SMEM_SZ>>>(out, R);
}

// round 7
// speedup vs baseline: 1.1821x; 1.1299x over previous
#include <cuda_runtime.h>
#include <cuda_bf16.h>
#include <cuda_fp16.h>
#include <cstdint>

// ---------------- static device scratch (no allocs allowed) ----------------
#define MAXR   32
#define EPB    4096
#define MAXBLK 1024
#define MAXE   2000000
#define MAXN   200000
#define NFB    128         // blocks: feat->fp16 conversion
#define NZB    128         // blocks: zero the output

__device__ int g_blockhist[MAXBLK * MAXR];
__device__ int g_blockbase[MAXBLK * MAXR];
__device__ int g_off[MAXR + 1];   // edge offsets per relation
__device__ int g_gs[MAXR + 1];    // group (4-tile) offsets per relation
__device__ int2 g_srcdst[MAXE];   // packed {src, dst} grouped by relation
__device__ __align__(16) __half g_fh[MAXN * 64];       // feat as fp16
// Pre-packed B fragments (mma.m16n8k16 register order), fp16 hi/lo split.
// Layout: [rel][ks(4)][ntg(8)][lane(32)] -> uint2 {b0, b1}
__device__ __align__(16) uint2 g_wfh[MAXR * 1024];
__device__ __align__(16) uint2 g_wfl[MAXR * 1024];

// ---------------- helpers ----------------
__device__ __forceinline__ uint32_t smem_u32(const void* p) {
    uint32_t a;
    asm("{ .reg .u64 t; cvta.to.shared.u64 t, %1; cvt.u32.u64 %0, t; }"
        : "=r"(a) : "l"(p));
    return a;
}

__device__ __forceinline__ uint32_t pack_h2(__half a, __half b) {
    __half2 t = __halves2half2(a, b);
    return *reinterpret_cast<uint32_t*>(&t);
}

__device__ __forceinline__ void mma16816(float* c, const uint32_t* a, const uint32_t* b) {
    asm volatile(
        "mma.sync.aligned.m16n8k16.row.col.f32.f16.f16.f32 "
        "{%0,%1,%2,%3}, {%4,%5,%6,%7}, {%8,%9}, {%0,%1,%2,%3};"
        : "+f"(c[0]), "+f"(c[1]), "+f"(c[2]), "+f"(c[3])
        : "r"(a[0]), "r"(a[1]), "r"(a[2]), "r"(a[3]), "r"(b[0]), "r"(b[1]));
}

__device__ __forceinline__ void ldsm4(uint32_t* r, uint32_t addr) {
    asm volatile("ldmatrix.sync.aligned.m8n8.x4.shared.b16 {%0,%1,%2,%3}, [%4];"
                 : "=r"(r[0]), "=r"(r[1]), "=r"(r[2]), "=r"(r[3]) : "r"(addr));
}

__device__ __forceinline__ void red4(float* p, float a, float b, float c, float d) {
    asm volatile("red.global.add.v4.f32 [%0], {%1, %2, %3, %4};"
                 :: "l"(p), "f"(a), "f"(b), "f"(c), "f"(d) : "memory");
}

// 128B-granular bulk async copy with mbarrier transaction accounting (sm_90+)
__device__ __forceinline__ void bulkcp(uint32_t dst, const void* src,
                                       uint32_t bytes, uint32_t mbar) {
    asm volatile(
        "cp.async.bulk.shared::cluster.global.mbarrier::complete_tx::bytes "
        "[%0], [%1], %2, [%3];"
        :: "r"(dst), "l"(src), "r"(bytes), "r"(mbar) : "memory");
}

__device__ __forceinline__ void mbar_init(uint32_t mbar, uint32_t cnt) {
    asm volatile("mbarrier.init.shared.b64 [%0], %1;" :: "r"(mbar), "r"(cnt) : "memory");
}

__device__ __forceinline__ void mbar_expect(uint32_t mbar, uint32_t tx) {
    asm volatile("mbarrier.arrive.expect_tx.shared.b64 _, [%0], %1;"
                 :: "r"(mbar), "r"(tx) : "memory");
}

__device__ __forceinline__ void mbar_wait(uint32_t mbar, uint32_t parity) {
    asm volatile(
        "{\n\t.reg .pred P1;\n\t"
        "WAIT_%=:\n\t"
        "mbarrier.try_wait.parity.acquire.cta.shared::cta.b64 P1, [%0], %1, 0x989680;\n\t"
        "@P1 bra.uni DONE_%=;\n\t"
        "bra.uni WAIT_%=;\n\t"
        "DONE_%=:\n\t}"
        :: "r"(mbar), "r"(parity) : "memory");
}

// ------- fused prep: W-frags + feat->fp16 + zero(out) + per-block hist ------
// Column permutation (changed this round for coalesced epilogue reds):
// logical col n(h, nt, p) = h*32 + (nt>>1)*16 + (p>>1)*4 + (nt&1)*2 + (p&1)
// => C-fragment thread m (phys cols 2m,2m+1) owns logical cols
//    {m*4..m*4+3} from nt=0,1 and {16+m*4..16+m*4+3} from nt=2,3:
//    each red4 warp-instruction covers 64B CONTIGUOUS per output row.
__global__ void k_prep_hist(const float* __restrict__ w, const float* __restrict__ feat,
                            const int* __restrict__ et, float* __restrict__ out,
                            int E, int R, int nfeat, int nout) {
    int bid = blockIdx.x;
    if (bid < R) {
        int r = bid;
        const float* wr = w + r * 4096;
        for (int idx = threadIdx.x; idx < 1024; idx += blockDim.x) {
            int lane = idx & 31, ntg = (idx >> 5) & 7, ks = idx >> 8;
            int h = ntg >> 2, nt = ntg & 3, p = lane >> 2;
            int n = h * 32 + (nt >> 1) * 16 + (p >> 1) * 4 + (nt & 1) * 2 + (p & 1);
            int k0 = ks * 16 + 2 * (lane & 3);
            float w00 = wr[k0 * 64 + n],       w01 = wr[(k0 + 1) * 64 + n];
            float w10 = wr[(k0 + 8) * 64 + n], w11 = wr[(k0 + 9) * 64 + n];
            __half h00 = __float2half_rn(w00), h01 = __float2half_rn(w01);
            __half h10 = __float2half_rn(w10), h11 = __float2half_rn(w11);
            __half l00 = __float2half_rn(w00 - __half2float(h00));
            __half l01 = __float2half_rn(w01 - __half2float(h01));
            __half l10 = __float2half_rn(w10 - __half2float(h10));
            __half l11 = __float2half_rn(w11 - __half2float(h11));
            g_wfh[r * 1024 + idx] = make_uint2(pack_h2(h00, h01), pack_h2(h10, h11));
            g_wfl[r * 1024 + idx] = make_uint2(pack_h2(l00, l01), pack_h2(l10, l11));
        }
    } else if (bid < R + NFB) {
        for (int i = (bid - R) * blockDim.x + threadIdx.x; i < nfeat / 2;
             i += NFB * blockDim.x) {
            float2 v = ((const float2*)feat)[i];
            ((uint32_t*)g_fh)[i] = pack_h2(__float2half_rn(v.x), __float2half_rn(v.y));
        }
    } else if (bid < R + NFB + NZB) {
        float4 z = make_float4(0.f, 0.f, 0.f, 0.f);
        for (int i = (bid - R - NFB) * blockDim.x + threadIdx.x; i < nout / 4;
             i += NZB * blockDim.x)
            ((float4*)out)[i] = z;
    } else {
        __shared__ int h[MAXR];
        int hb = bid - R - NFB - NZB;
        if (threadIdx.x < MAXR) h[threadIdx.x] = 0;
        __syncthreads();
        int start = hb * EPB, end = min(start + EPB, E);
        for (int i = start + threadIdx.x; i < end; i += blockDim.x)
            atomicAdd(&h[et[i]], 1);
        __syncthreads();
        if (threadIdx.x < MAXR)
            g_blockhist[hb * MAXR + threadIdx.x] = h[threadIdx.x];
    }
}

// ------- parallel scan: warp r owns relation r, lanes chunk the blocks ------
__global__ void k_scan(int nblocks, int R) {
    __shared__ int tot[MAXR];
    __shared__ int off[MAXR + 1];
    int w = threadIdx.x >> 5, j = threadIdx.x & 31;
    int C = (nblocks + 31) / 32;
    int b0 = min(j * C, nblocks), b1 = min(b0 + C, nblocks);
    int s = 0;
    if (w < R)
        for (int b = b0; b < b1; b++) s += g_blockhist[b * MAXR + w];
    int ssum = s;
#pragma unroll
    for (int d = 1; d < 32; d <<= 1) {
        int v = __shfl_up_sync(0xffffffffu, ssum, d);
        if (j >= d) ssum += v;
    }
    int total = __shfl_sync(0xffffffffu, ssum, 31);
    int excl = ssum - s;
    if (w < R && j == 0) tot[w] = total;
    __syncthreads();
    if (threadIdx.x == 0) {
        int acc = 0, gs = 0;
        for (int i = 0; i < R; i++) {
            off[i] = acc; g_off[i] = acc; acc += tot[i];
            g_gs[i] = gs; gs += (((tot[i] + 127) >> 7) + 3) >> 2;
        }
        off[R] = acc; g_off[R] = acc; g_gs[R] = gs;
    }
    __syncthreads();
    if (w < R) {
        int base = off[w] + excl;
        for (int b = b0; b < b1; b++) {
            g_blockbase[b * MAXR + w] = base;
            base += g_blockhist[b * MAXR + w];
        }
    }
}

// scatter with warp-aggregated smem atomics (match_any on relation)
__global__ void k_scatter(const int* __restrict__ et, const int* __restrict__ src,
                          const int* __restrict__ dst, int E) {
    __shared__ int cur[MAXR];
    if (threadIdx.x < MAXR)
        cur[threadIdx.x] = g_blockbase[blockIdx.x * MAXR + threadIdx.x];
    __syncthreads();
    int start = blockIdx.x * EPB, end = min(start + EPB, E);
    for (int i = start + threadIdx.x; i < end; i += blockDim.x) {
        int r = et[i];
        unsigned act = __activemask();
        unsigned mask = __match_any_sync(act, r);
        int leader = __ffs(mask) - 1;
        int rank = __popc(mask & ((1u << (threadIdx.x & 31)) - 1));
        int base = 0;
        if ((int)(threadIdx.x & 31) == leader)
            base = atomicAdd(&cur[r], __popc(mask));
        base = __shfl_sync(act, base, leader);
        g_srcdst[base + rank] = make_int2(src[i], dst[i]);
    }
}

// ---------------- main ----------------
// SMEM: A fp16 128 rows x 144B pitch, double-buffered (bulk-copied, unswizzled;
// pitch 144 keeps ldmatrix conflict-free); B frag hi+lo 16KB; dst x2; mbar x2.
#define APITCH  144
#define SM_A0   0              // 128*144 = 18432
#define SM_A1   18432
#define SM_BH   36864
#define SM_BL   45056
#define SM_DST0 53248
#define SM_DST1 53760
#define SM_CTRL 54272
#define SM_MBAR 54288          // two b64 mbarriers
#define SMEM_SZ 54336

__global__ __launch_bounds__(256, 4) void k_main(float* __restrict__ out, int R)
{
    extern __shared__ char smem[];
    int tid = threadIdx.x;

    if ((int)blockIdx.x >= g_gs[R]) return;

    uint32_t sbase = smem_u32(smem);
    uint32_t mb0 = sbase + SM_MBAR, mb1 = sbase + SM_MBAR + 8;
    int* ctrl = (int*)(smem + SM_CTRL);
    if (tid == 0) {
        int b = blockIdx.x, r = 0;
        while (b >= g_gs[r + 1]) r++;
        int tile0 = (b - g_gs[r]) * 4;
        int ebase = g_off[r] + tile0 * 128;
        int erem = g_off[r + 1] - ebase;
        ctrl[0] = r;
        ctrl[1] = ebase;
        ctrl[2] = erem;
        ctrl[3] = min(4, (erem + 127) >> 7);
        mbar_init(mb0, 1);
        mbar_init(mb1, 1);
    }
    __syncthreads();
    int rel = ctrl[0], ebase = ctrl[1], erem = ctrl[2], ntile = ctrl[3];

    // ---- prologue: B (2 bulk copies) + tile-0 rows (128 bulk copies) ----
    {
        int cnt0 = min(128, erem);
        if (tid == 0) {
            mbar_expect(mb0, 16384u + (uint32_t)cnt0 * 128u);
            bulkcp(sbase + SM_BH, g_wfh + (size_t)rel * 1024, 8192, mb0);
            bulkcp(sbase + SM_BL, g_wfl + (size_t)rel * 1024, 8192, mb0);
        }
        if (tid < 128) {
            int row = tid;
            if (row < cnt0) {
                int2 e = g_srcdst[ebase + row];
                ((int*)(smem + SM_DST0))[row] = e.y;
                bulkcp(sbase + SM_A0 + row * APITCH,
                       g_fh + (size_t)e.x * 64, 128, mb0);
            } else {
                ((int*)(smem + SM_DST0))[row] = 0;
                uint4 z = make_uint4(0, 0, 0, 0);
#pragma unroll
                for (int i = 0; i < 8; i++)
                    *(uint4*)(smem + SM_A0 + row * APITCH + i * 16) = z;
            }
        }
    }

    int w = tid >> 5, lane = tid & 31;
    int mrow = (w & 3) * 32, h = w >> 2;
    int q = lane >> 2, m = lane & 3;
    int lrow = (lane & 7) + ((lane >> 3) & 1) * 8;
    int lkh = lane >> 4;

    for (int t = 0; t < ntile; t++) {
        int cnt = min(128, erem - t * 128);
        int abuf = (t & 1) ? SM_A1 : SM_A0;
        int dbuf = (t & 1) ? SM_DST1 : SM_DST0;

        // prefetch tile t+1 into the other buffer (other mbarrier)
        if (t + 1 < ntile) {
            int nbuf = ((t + 1) & 1) ? SM_A1 : SM_A0;
            int ndst = ((t + 1) & 1) ? SM_DST1 : SM_DST0;
            uint32_t nmb = ((t + 1) & 1) ? mb1 : mb0;
            int cnt1 = min(128, erem - (t + 1) * 128);
            if (tid == 0) mbar_expect(nmb, (uint32_t)cnt1 * 128u);
            if (tid < 128) {
                int row = tid;
                if (row < cnt1) {
                    int2 e = g_srcdst[ebase + (t + 1) * 128 + row];
                    ((int*)(smem + ndst))[row] = e.y;
                    bulkcp(sbase + nbuf + row * APITCH,
                           g_fh + (size_t)e.x * 64, 128, nmb);
                } else {
                    ((int*)(smem + ndst))[row] = 0;
                    uint4 z = make_uint4(0, 0, 0, 0);
#pragma unroll
                    for (int i = 0; i < 8; i++)
                        *(uint4*)(smem + nbuf + row * APITCH + i * 16) = z;
                }
            }
        }

        // wait tile t's data
        mbar_wait((t & 1) ? mb1 : mb0, (t >> 1) & 1);
        __syncthreads();

        // ---- compute: warp tile 32 rows x 32 cols, 2-term fp16 ----
        float acc[2][4][4];
#pragma unroll
        for (int a = 0; a < 2; a++)
#pragma unroll
            for (int b = 0; b < 4; b++)
#pragma unroll
                for (int c = 0; c < 4; c++) acc[a][b][c] = 0.0f;

#pragma unroll
        for (int ks = 0; ks < 4; ks++) {
            int kchunk = ks * 2 + lkh;
            uint32_t af[2][4];
#pragma unroll
            for (int mt = 0; mt < 2; mt++) {
                int arow = mrow + mt * 16 + lrow;
                ldsm4(af[mt], sbase + abuf + arow * APITCH + kchunk * 16);
            }
            const uint2* Bh = (const uint2*)(smem + SM_BH) + (ks * 8 + h * 4) * 32 + lane;
            const uint2* Bl = (const uint2*)(smem + SM_BL) + (ks * 8 + h * 4) * 32 + lane;
#pragma unroll
            for (int nt = 0; nt < 4; nt++) {
                uint2 bh = Bh[nt * 32];
                uint2 bl = Bl[nt * 32];
#pragma unroll
                for (int mt = 0; mt < 2; mt++) {
                    mma16816(acc[mt][nt], af[mt], (const uint32_t*)&bh);  // F*Wh
                    mma16816(acc[mt][nt], af[mt], (const uint32_t*)&bl);  // F*Wl
                }
            }
        }

        // ---- epilogue: coalesced reds — each red4 instr covers 64B/row ----
        // thread m owns cols [m*4, m*4+4) (nt 0,1) and [16+m*4, ..) (nt 2,3)
        const int* db = (const int*)(smem + dbuf);
#pragma unroll
        for (int mt = 0; mt < 2; mt++)
#pragma unroll
            for (int hf = 0; hf < 2; hf++) {
                int row = mrow + mt * 16 + hf * 8 + q;
                if (row < cnt) {
                    int j = hf * 2;
                    float* o = out + (size_t)db[row] * 64 + h * 32 + m * 4;
                    red4(o,      acc[mt][0][j], acc[mt][0][j + 1],
                                 acc[mt][1][j], acc[mt][1][j + 1]);
                    red4(o + 16, acc[mt][2][j], acc[mt][2][j + 1],
                                 acc[mt][3][j], acc[mt][3][j + 1]);
                }
            }
        __syncthreads();   // buffer free before next prefetch overwrites it
    }
}

// ---------------- launch ----------------
extern "C" void kernel_launch(void* const* d_in, const int* in_sizes, int n_in,
                              void* d_out, int out_size) {
    const float* feat   = (const float*)d_in[0];
    const float* weight = (const float*)d_in[1];
    const int*   src    = (const int*)d_in[2];
    const int*   dst    = (const int*)d_in[3];
    const int*   et     = (const int*)d_in[4];

    int E = in_sizes[2];
    int R = in_sizes[1] / 4096;   // 64*64 per relation
    int nfeat = in_sizes[0];
    float* out = (float*)d_out;

    int nblocks = (E + EPB - 1) / EPB;
    k_prep_hist<<<R + NFB + NZB + nblocks, 256>>>(weight, feat, et, out,
                                                  E, R, nfeat, out_size);
    k_scan<<<1, 1024>>>(nblocks, R);
    k_scatter<<<nblocks, 256>>>(et, src, dst, E);

    int ngroups = (E + 511) / 512 + R;   // upper bound; extras exit via g_gs[R]
    static int smem_set = 0;
    if (!smem_set) {
        cudaFuncSetAttribute(k_main, cudaFuncAttributeMaxDynamicSharedMemorySize, SMEM_SZ);
        smem_set = 1;
    }
    k_main<<<ngroups, 256, SMEM_SZ>>>(out, R);
}

// round 8
// speedup vs baseline: 1.2340x; 1.0439x over previous
#include <cuda_runtime.h>
#include <cuda_bf16.h>
#include <cuda_fp16.h>
#include <cstdint>

// ---------------- static device scratch (no allocs allowed) ----------------
#define MAXR   32
#define EPB    4096
#define MAXBLK 1024
#define MAXE   2000000
#define MAXN   200000
#define NFB    128         // blocks: feat->fp16 conversion
#define NZB    128         // blocks: zero the output

__device__ int g_blockhist[MAXBLK * MAXR];
__device__ int g_blockbase[MAXBLK * MAXR];
__device__ int g_off[MAXR + 1];   // edge offsets per relation
__device__ int g_gs[MAXR + 1];    // group (4-tile) offsets per relation
__device__ int2 g_srcdst[MAXE];   // packed {src, dst} grouped by relation
__device__ __align__(16) __half g_fh[MAXN * 64];       // feat as fp16
// Pre-packed B fragments (mma.m16n8k16 register order), fp16 (hi only).
// Layout: [rel][ks(4)][ntg(8)][lane(32)] -> uint2 {b0, b1}
__device__ __align__(16) uint2 g_wfh[MAXR * 1024];

// ---------------- helpers ----------------
__device__ __forceinline__ uint32_t smem_u32(const void* p) {
    uint32_t a;
    asm("{ .reg .u64 t; cvta.to.shared.u64 t, %1; cvt.u32.u64 %0, t; }"
        : "=r"(a) : "l"(p));
    return a;
}

__device__ __forceinline__ uint32_t pack_h2(__half a, __half b) {
    __half2 t = __halves2half2(a, b);
    return *reinterpret_cast<uint32_t*>(&t);
}

__device__ __forceinline__ void mma16816(float* c, const uint32_t* a, const uint32_t* b) {
    asm volatile(
        "mma.sync.aligned.m16n8k16.row.col.f32.f16.f16.f32 "
        "{%0,%1,%2,%3}, {%4,%5,%6,%7}, {%8,%9}, {%0,%1,%2,%3};"
        : "+f"(c[0]), "+f"(c[1]), "+f"(c[2]), "+f"(c[3])
        : "r"(a[0]), "r"(a[1]), "r"(a[2]), "r"(a[3]), "r"(b[0]), "r"(b[1]));
}

__device__ __forceinline__ void ldsm4(uint32_t* r, uint32_t addr) {
    asm volatile("ldmatrix.sync.aligned.m8n8.x4.shared.b16 {%0,%1,%2,%3}, [%4];"
                 : "=r"(r[0]), "=r"(r[1]), "=r"(r[2]), "=r"(r[3]) : "r"(addr));
}

__device__ __forceinline__ void red4(float* p, float a, float b, float c, float d) {
    asm volatile("red.global.add.v4.f32 [%0], {%1, %2, %3, %4};"
                 :: "l"(p), "f"(a), "f"(b), "f"(c), "f"(d) : "memory");
}

// 128B-granular bulk async copy with mbarrier transaction accounting (sm_90+)
__device__ __forceinline__ void bulkcp(uint32_t dst, const void* src,
                                       uint32_t bytes, uint32_t mbar) {
    asm volatile(
        "cp.async.bulk.shared::cluster.global.mbarrier::complete_tx::bytes "
        "[%0], [%1], %2, [%3];"
        :: "r"(dst), "l"(src), "r"(bytes), "r"(mbar) : "memory");
}

__device__ __forceinline__ void mbar_init(uint32_t mbar, uint32_t cnt) {
    asm volatile("mbarrier.init.shared.b64 [%0], %1;" :: "r"(mbar), "r"(cnt) : "memory");
}

__device__ __forceinline__ void mbar_expect(uint32_t mbar, uint32_t tx) {
    asm volatile("mbarrier.arrive.expect_tx.shared.b64 _, [%0], %1;"
                 :: "r"(mbar), "r"(tx) : "memory");
}

__device__ __forceinline__ void mbar_wait(uint32_t mbar, uint32_t parity) {
    asm volatile(
        "{\n\t.reg .pred P1;\n\t"
        "WAIT_%=:\n\t"
        "mbarrier.try_wait.parity.acquire.cta.shared::cta.b64 P1, [%0], %1, 0x989680;\n\t"
        "@P1 bra.uni DONE_%=;\n\t"
        "bra.uni WAIT_%=;\n\t"
        "DONE_%=:\n\t}"
        :: "r"(mbar), "r"(parity) : "memory");
}

// ------- fused prep: W-frags + feat->fp16 + zero(out) + per-block hist ------
// Column permutation (coalesced epilogue reds):
// logical col n(h, nt, p) = h*32 + (nt>>1)*16 + (p>>1)*4 + (nt&1)*2 + (p&1)
__global__ void k_prep_hist(const float* __restrict__ w, const float* __restrict__ feat,
                            const int* __restrict__ et, float* __restrict__ out,
                            int E, int R, int nfeat, int nout) {
    int bid = blockIdx.x;
    if (bid < R) {
        int r = bid;
        const float* wr = w + r * 4096;
        for (int idx = threadIdx.x; idx < 1024; idx += blockDim.x) {
            int lane = idx & 31, ntg = (idx >> 5) & 7, ks = idx >> 8;
            int h = ntg >> 2, nt = ntg & 3, p = lane >> 2;
            int n = h * 32 + (nt >> 1) * 16 + (p >> 1) * 4 + (nt & 1) * 2 + (p & 1);
            int k0 = ks * 16 + 2 * (lane & 3);
            g_wfh[r * 1024 + idx] = make_uint2(
                pack_h2(__float2half_rn(wr[k0 * 64 + n]),
                        __float2half_rn(wr[(k0 + 1) * 64 + n])),
                pack_h2(__float2half_rn(wr[(k0 + 8) * 64 + n]),
                        __float2half_rn(wr[(k0 + 9) * 64 + n])));
        }
    } else if (bid < R + NFB) {
        for (int i = (bid - R) * blockDim.x + threadIdx.x; i < nfeat / 2;
             i += NFB * blockDim.x) {
            float2 v = ((const float2*)feat)[i];
            ((uint32_t*)g_fh)[i] = pack_h2(__float2half_rn(v.x), __float2half_rn(v.y));
        }
    } else if (bid < R + NFB + NZB) {
        float4 z = make_float4(0.f, 0.f, 0.f, 0.f);
        for (int i = (bid - R - NFB) * blockDim.x + threadIdx.x; i < nout / 4;
             i += NZB * blockDim.x)
            ((float4*)out)[i] = z;
    } else {
        __shared__ int h[MAXR];
        int hb = bid - R - NFB - NZB;
        if (threadIdx.x < MAXR) h[threadIdx.x] = 0;
        __syncthreads();
        int start = hb * EPB, end = min(start + EPB, E);
        for (int i = start + threadIdx.x; i < end; i += blockDim.x)
            atomicAdd(&h[et[i]], 1);
        __syncthreads();
        if (threadIdx.x < MAXR)
            g_blockhist[hb * MAXR + threadIdx.x] = h[threadIdx.x];
    }
}

// ------- parallel scan: warp r owns relation r, lanes chunk the blocks ------
__global__ void k_scan(int nblocks, int R) {
    __shared__ int tot[MAXR];
    __shared__ int off[MAXR + 1];
    int w = threadIdx.x >> 5, j = threadIdx.x & 31;
    int C = (nblocks + 31) / 32;
    int b0 = min(j * C, nblocks), b1 = min(b0 + C, nblocks);
    int s = 0;
    if (w < R)
        for (int b = b0; b < b1; b++) s += g_blockhist[b * MAXR + w];
    int ssum = s;
#pragma unroll
    for (int d = 1; d < 32; d <<= 1) {
        int v = __shfl_up_sync(0xffffffffu, ssum, d);
        if (j >= d) ssum += v;
    }
    int total = __shfl_sync(0xffffffffu, ssum, 31);
    int excl = ssum - s;
    if (w < R && j == 0) tot[w] = total;
    __syncthreads();
    if (threadIdx.x == 0) {
        int acc = 0, gs = 0;
        for (int i = 0; i < R; i++) {
            off[i] = acc; g_off[i] = acc; acc += tot[i];
            g_gs[i] = gs; gs += (((tot[i] + 127) >> 7) + 3) >> 2;
        }
        off[R] = acc; g_off[R] = acc; g_gs[R] = gs;
    }
    __syncthreads();
    if (w < R) {
        int base = off[w] + excl;
        for (int b = b0; b < b1; b++) {
            g_blockbase[b * MAXR + w] = base;
            base += g_blockhist[b * MAXR + w];
        }
    }
}

// scatter with warp-aggregated smem atomics (match_any on relation)
__global__ void k_scatter(const int* __restrict__ et, const int* __restrict__ src,
                          const int* __restrict__ dst, int E) {
    __shared__ int cur[MAXR];
    if (threadIdx.x < MAXR)
        cur[threadIdx.x] = g_blockbase[blockIdx.x * MAXR + threadIdx.x];
    __syncthreads();
    int start = blockIdx.x * EPB, end = min(start + EPB, E);
    for (int i = start + threadIdx.x; i < end; i += blockDim.x) {
        int r = et[i];
        unsigned act = __activemask();
        unsigned mask = __match_any_sync(act, r);
        int leader = __ffs(mask) - 1;
        int rank = __popc(mask & ((1u << (threadIdx.x & 31)) - 1));
        int base = 0;
        if ((int)(threadIdx.x & 31) == leader)
            base = atomicAdd(&cur[r], __popc(mask));
        base = __shfl_sync(act, base, leader);
        g_srcdst[base + rank] = make_int2(src[i], dst[i]);
    }
}

// ---------------- main ----------------
// SMEM: A fp16 128 rows x 144B pitch, double-buffered (bulk-copied, unswizzled;
// pitch 144 keeps ldmatrix conflict-free); B frag 8KB; dst x2; mbar x2.
#define APITCH  144
#define SM_A0   0              // 128*144 = 18432
#define SM_A1   18432
#define SM_BH   36864          // 8192
#define SM_DST0 45056
#define SM_DST1 45568
#define SM_CTRL 46080
#define SM_MBAR 46096          // two b64 mbarriers
#define SMEM_SZ 46144

__global__ __launch_bounds__(256, 4) void k_main(float* __restrict__ out, int R)
{
    extern __shared__ char smem[];
    int tid = threadIdx.x;

    if ((int)blockIdx.x >= g_gs[R]) return;

    uint32_t sbase = smem_u32(smem);
    uint32_t mb0 = sbase + SM_MBAR, mb1 = sbase + SM_MBAR + 8;
    int* ctrl = (int*)(smem + SM_CTRL);
    if (tid == 0) {
        int b = blockIdx.x, r = 0;
        while (b >= g_gs[r + 1]) r++;
        int tile0 = (b - g_gs[r]) * 4;
        int ebase = g_off[r] + tile0 * 128;
        int erem = g_off[r + 1] - ebase;
        ctrl[0] = r;
        ctrl[1] = ebase;
        ctrl[2] = erem;
        ctrl[3] = min(4, (erem + 127) >> 7);
        mbar_init(mb0, 1);
        mbar_init(mb1, 1);
    }
    __syncthreads();
    int rel = ctrl[0], ebase = ctrl[1], erem = ctrl[2], ntile = ctrl[3];

    // ---- prologue: B (1 bulk copy) + tile-0 rows (bulk copies) ----
    {
        int cnt0 = min(128, erem);
        if (tid == 0) {
            mbar_expect(mb0, 8192u + (uint32_t)cnt0 * 128u);
            bulkcp(sbase + SM_BH, g_wfh + (size_t)rel * 1024, 8192, mb0);
        }
        if (tid < 128) {
            int row = tid;
            if (row < cnt0) {
                int2 e = g_srcdst[ebase + row];
                ((int*)(smem + SM_DST0))[row] = e.y;
                bulkcp(sbase + SM_A0 + row * APITCH,
                       g_fh + (size_t)e.x * 64, 128, mb0);
            } else {
                ((int*)(smem + SM_DST0))[row] = 0;
                uint4 z = make_uint4(0, 0, 0, 0);
#pragma unroll
                for (int i = 0; i < 8; i++)
                    *(uint4*)(smem + SM_A0 + row * APITCH + i * 16) = z;
            }
        }
    }

    int w = tid >> 5, lane = tid & 31;
    int mrow = (w & 3) * 32, h = w >> 2;
    int q = lane >> 2, m = lane & 3;
    int lrow = (lane & 7) + ((lane >> 3) & 1) * 8;
    int lkh = lane >> 4;

    for (int t = 0; t < ntile; t++) {
        int cnt = min(128, erem - t * 128);
        int abuf = (t & 1) ? SM_A1 : SM_A0;
        int dbuf = (t & 1) ? SM_DST1 : SM_DST0;

        // prefetch tile t+1 into the other buffer (other mbarrier)
        if (t + 1 < ntile) {
            int nbuf = ((t + 1) & 1) ? SM_A1 : SM_A0;
            int ndst = ((t + 1) & 1) ? SM_DST1 : SM_DST0;
            uint32_t nmb = ((t + 1) & 1) ? mb1 : mb0;
            int cnt1 = min(128, erem - (t + 1) * 128);
            if (tid == 0) mbar_expect(nmb, (uint32_t)cnt1 * 128u);
            if (tid < 128) {
                int row = tid;
                if (row < cnt1) {
                    int2 e = g_srcdst[ebase + (t + 1) * 128 + row];
                    ((int*)(smem + ndst))[row] = e.y;
                    bulkcp(sbase + nbuf + row * APITCH,
                           g_fh + (size_t)e.x * 64, 128, nmb);
                } else {
                    ((int*)(smem + ndst))[row] = 0;
                    uint4 z = make_uint4(0, 0, 0, 0);
#pragma unroll
                    for (int i = 0; i < 8; i++)
                        *(uint4*)(smem + nbuf + row * APITCH + i * 16) = z;
                }
            }
        }

        // wait tile t's data
        mbar_wait((t & 1) ? mb1 : mb0, (t >> 1) & 1);
        __syncthreads();

        // ---- compute: warp tile 32 rows x 32 cols, fp16 single-term ----
        float acc[2][4][4];
#pragma unroll
        for (int a = 0; a < 2; a++)
#pragma unroll
            for (int b = 0; b < 4; b++)
#pragma unroll
                for (int c = 0; c < 4; c++) acc[a][b][c] = 0.0f;

#pragma unroll
        for (int ks = 0; ks < 4; ks++) {
            int kchunk = ks * 2 + lkh;
            uint32_t af[2][4];
#pragma unroll
            for (int mt = 0; mt < 2; mt++) {
                int arow = mrow + mt * 16 + lrow;
                ldsm4(af[mt], sbase + abuf + arow * APITCH + kchunk * 16);
            }
            const uint2* Bh = (const uint2*)(smem + SM_BH) + (ks * 8 + h * 4) * 32 + lane;
#pragma unroll
            for (int nt = 0; nt < 4; nt++) {
                uint2 bh = Bh[nt * 32];
#pragma unroll
                for (int mt = 0; mt < 2; mt++)
                    mma16816(acc[mt][nt], af[mt], (const uint32_t*)&bh);
            }
        }

        // ---- epilogue: coalesced reds — each red4 instr covers 64B/row ----
        const int* db = (const int*)(smem + dbuf);
#pragma unroll
        for (int mt = 0; mt < 2; mt++)
#pragma unroll
            for (int hf = 0; hf < 2; hf++) {
                int row = mrow + mt * 16 + hf * 8 + q;
                if (row < cnt) {
                    int j = hf * 2;
                    float* o = out + (size_t)db[row] * 64 + h * 32 + m * 4;
                    red4(o,      acc[mt][0][j], acc[mt][0][j + 1],
                                 acc[mt][1][j], acc[mt][1][j + 1]);
                    red4(o + 16, acc[mt][2][j], acc[mt][2][j + 1],
                                 acc[mt][3][j], acc[mt][3][j + 1]);
                }
            }
        __syncthreads();   // buffer free before next prefetch overwrites it
    }
}

// ---------------- launch ----------------
extern "C" void kernel_launch(void* const* d_in, const int* in_sizes, int n_in,
                              void* d_out, int out_size) {
    const float* feat   = (const float*)d_in[0];
    const float* weight = (const float*)d_in[1];
    const int*   src    = (const int*)d_in[2];
    const int*   dst    = (const int*)d_in[3];
    const int*   et     = (const int*)d_in[4];

    int E = in_sizes[2];
    int R = in_sizes[1] / 4096;   // 64*64 per relation
    int nfeat = in_sizes[0];
    float* out = (float*)d_out;

    int nblocks = (E + EPB - 1) / EPB;
    k_prep_hist<<<R + NFB + NZB + nblocks, 256>>>(weight, feat, et, out,
                                                  E, R, nfeat, out_size);
    k_scan<<<1, 1024>>>(nblocks, R);
    k_scatter<<<nblocks, 256>>>(et, src, dst, E);

    int ngroups = (E + 511) / 512 + R;   // upper bound; extras exit via g_gs[R]
    static int smem_set = 0;
    if (!smem_set) {
        cudaFuncSetAttribute(k_main, cudaFuncAttributeMaxDynamicSharedMemorySize, SMEM_SZ);
        smem_set = 1;
    }
    k_main<<<ngroups, 256, SMEM_SZ>>>(out, R);
}